// round 9
// baseline (speedup 1.0000x reference)
#include <cuda_runtime.h>
#include <math.h>
#include <stdint.h>

#define T_TOK 8192
#define DM    512
#define DFF   2048
#define NE    64
#define CAP   320
#define CAPP  384   // padded capacity (3 x 128)

// ---------------- scratch ----------------------------------------------------
__device__ int   g_flat_e[T_TOK * 2];
__device__ int   g_entry_slot[T_TOK * 2];
__device__ int   g_slot_tok[NE * CAPP];
__device__ float g_xt[(size_t)T_TOK * DM];       // x pre-rounded to tf32
__device__ float g_H[(size_t)NE * CAPP * DFF];   // stored tf32-rounded
__device__ float g_Y[(size_t)NE * CAPP * DM];

// ---------------- helpers ----------------------------------------------------
__device__ __forceinline__ uint32_t smem_u32(const void* p) {
    uint32_t a;
    asm("{ .reg .u64 t; cvta.to.shared.u64 t, %1; cvt.u32.u64 %0, t; }"
        : "=r"(a) : "l"(p));
    return a;
}
__device__ __forceinline__ uint32_t cvt_tf32(float f) {
    uint32_t r; asm("cvt.rna.tf32.f32 %0, %1;" : "=r"(r) : "f"(f)); return r;
}
__device__ __forceinline__ uint4 cvt4(float4 v) {
    uint4 t;
    t.x = cvt_tf32(v.x); t.y = cvt_tf32(v.y);
    t.z = cvt_tf32(v.z); t.w = cvt_tf32(v.w);
    return t;
}
__device__ __forceinline__ void ldsm4(uint32_t* r, uint32_t addr) {
    asm volatile("ldmatrix.sync.aligned.m8n8.x4.shared.b16 {%0,%1,%2,%3}, [%4];"
                 : "=r"(r[0]), "=r"(r[1]), "=r"(r[2]), "=r"(r[3]) : "r"(addr));
}
__device__ __forceinline__ void lds128(uint32_t* r, uint32_t addr) {
    asm volatile("ld.shared.v4.b32 {%0,%1,%2,%3}, [%4];"
                 : "=r"(r[0]), "=r"(r[1]), "=r"(r[2]), "=r"(r[3]) : "r"(addr));
}
__device__ __forceinline__ void cp16(uint32_t dst, const void* src, int srcsize) {
    asm volatile("cp.async.cg.shared.global [%0], [%1], 16, %2;"
                 :: "r"(dst), "l"(src), "r"(srcsize));
}
__device__ __forceinline__ void cp_commit() {
    asm volatile("cp.async.commit_group;" ::: "memory");
}
__device__ __forceinline__ void cp_wait0() {
    asm volatile("cp.async.wait_group 0;" ::: "memory");
}
__device__ __forceinline__ void mma8(float* d, const uint32_t* a, const uint32_t* b) {
    asm volatile("mma.sync.aligned.m16n8k8.row.col.f32.tf32.tf32.f32 "
                 "{%0,%1,%2,%3}, {%4,%5,%6,%7}, {%8,%9}, {%0,%1,%2,%3};"
                 : "+f"(d[0]), "+f"(d[1]), "+f"(d[2]), "+f"(d[3])
                 : "r"(a[0]), "r"(a[1]), "r"(a[2]), "r"(a[3]),
                   "r"(b[0]), "r"(b[1]));
}
__device__ __forceinline__ float gelu_f(float h) {
    return 0.5f * h * (1.0f + erff(h * 0.70710678118654752f));
}
__device__ __forceinline__ float gelu_t(float h) {   // gelu rounded to tf32
    return __uint_as_float(cvt_tf32(gelu_f(h)));
}

// smem geometry (bytes)
#define A_STRIDE 144                        // 32 k-floats + 4 pad
#define A_BUF    (128 * A_STRIDE)           // 18432
#define BP_BUF   32768                      // permuted B: 2 halves x 16KB
#define SMEM_TOT (2 * A_BUF + 2 * BP_BUF)   // 102400

// ---------------- 0) pre-round x to tf32 -------------------------------------
__global__ void cvt_x_kernel(const float* __restrict__ x) {
    int idx = blockIdx.x * blockDim.x + threadIdx.x;
    if (idx >= T_TOK * DM / 4) return;
    float4 v = *(const float4*)(x + (size_t)idx * 4);
    uint4 t = cvt4(v);
    *(uint4*)(g_xt + (size_t)idx * 4) = t;
}

// ---------------- 1) routing -------------------------------------------------
__global__ void route_kernel(const float* __restrict__ x,
                             const float* __restrict__ Wh) {
    int gw   = (blockIdx.x * blockDim.x + threadIdx.x) >> 5;
    int lane = threadIdx.x & 31;
    if (gw >= T_TOK) return;
    const float* xr = x + (size_t)gw * DM;
    float d0 = 0.f, d1 = 0.f;
    #pragma unroll
    for (int j = lane; j < DM; j += 32) {
        float v = xr[j];
        d0 = fmaf(v, Wh[j],      d0);
        d1 = fmaf(v, Wh[DM + j], d1);
    }
    #pragma unroll
    for (int o = 16; o > 0; o >>= 1) {
        d0 += __shfl_down_sync(0xffffffffu, d0, o);
        d1 += __shfl_down_sync(0xffffffffu, d1, o);
    }
    if (lane == 0) {
        g_flat_e[2 * gw]     = ((int)floorf(d0 * 8.0f)) & 63;
        g_flat_e[2 * gw + 1] = ((int)floorf(d1 * 8.0f)) & 63;
    }
}

// ---------------- 2) order-preserving rank -----------------------------------
__global__ void rank_kernel() {
    __shared__ int counts[NE];
    __shared__ int whist[32][NE];
    __shared__ int wpref[32][NE];
    __shared__ int ttot[NE];
    int tid  = threadIdx.x;
    int w    = tid >> 5;
    int lane = tid & 31;
    unsigned lmask = (1u << lane) - 1u;

    if (tid < NE) counts[tid] = 0;
    for (int j = tid; j < NE * CAPP; j += 1024) g_slot_tok[j] = -1;
    __syncthreads();

    for (int tile = 0; tile < (T_TOK * 2) / 1024; tile++) {
        for (int j = tid; j < 32 * NE; j += 1024) (&whist[0][0])[j] = 0;
        __syncthreads();

        int i = tile * 1024 + tid;
        int e = g_flat_e[i];
        unsigned m  = __match_any_sync(0xffffffffu, e);
        int prior   = __popc(m & lmask);
        if ((m & lmask) == 0) whist[w][e] = __popc(m);
        __syncthreads();

        if (tid < NE) {
            int s = 0;
            #pragma unroll
            for (int ww = 0; ww < 32; ww++) { wpref[ww][tid] = s; s += whist[ww][tid]; }
            ttot[tid] = s;
        }
        __syncthreads();

        int pos = counts[e] + wpref[w][e] + prior;
        if (pos < CAP) {
            g_entry_slot[i]            = e * CAPP + pos;
            g_slot_tok[e * CAPP + pos] = i >> 1;
        } else {
            g_entry_slot[i] = -1;
        }
        __syncthreads();
        if (tid < NE) counts[tid] += ttot[tid];
        __syncthreads();
    }
}

// Permuted-B addressing, per 128-wide half (unchanged formula):
//  f = q ^ (wn<<1) ^ (g>>2); word = ((ks*2+wn)*32 + q*8+g)*16 + ((v^f)<<2) + (w&3)

// ---------------- 3) GEMM1: H = gelu(gather(x_t) @ W1 + b1) ------------------
// CTA tile 128m x 256n, 8 warps as 2m x 4n, warp tile 64x64 (MF=4, NF=8)
__global__ __launch_bounds__(256) void xw1_kernel(
        const float* __restrict__ W1, const float* __restrict__ b1) {
    extern __shared__ char smem[];
    uint32_t sb = smem_u32(smem);
    int tid = threadIdx.x, lane = tid & 31, wid = tid >> 5;
    int wm = wid & 1, wh = wid >> 1;          // 2 m-halves x 4 n-quarters
    int g = lane >> 2, q = lane & 3;
    int n0 = blockIdx.x * 256, mt = blockIdx.y, e = blockIdx.z;

    const float* Wb = W1 + (size_t)e * DM * DFF;

    int tok[4];
    #pragma unroll
    for (int i = 0; i < 4; i++)
        tok[i] = g_slot_tok[e * CAPP + mt * 128 + (tid >> 3) + 32 * i];

    float acc[4][8][4];
    #pragma unroll
    for (int mf = 0; mf < 4; mf++)
        #pragma unroll
        for (int nf = 0; nf < 8; nf++)
            #pragma unroll
            for (int j = 0; j < 4; j++) acc[mf][nf][j] = 0.f;

    float4 regB[2][4];
    int akq = (tid & 7) * 4;

    int qw = wid & 3, kbw = (wid >> 2) & 1;
    uint32_t boff[4];
    #pragma unroll
    for (int j = 0; j < 4; j++) {
        int n = lane * 4 + j;                  // within a 128-half
        int wnn = n >> 6, nf = (n >> 3) & 7, gg = n & 7;
        int w = nf * 2 + kbw, vv = w >> 2;
        int ff = qw ^ (wnn << 1) ^ (gg >> 2);
        boff[j] = (uint32_t)(((wnn * 32 + qw * 8 + gg) * 16 + ((vv ^ ff) << 2) + (w & 3)) * 4);
    }

    auto cpA = [&](int c) {
        int st = c & 1, k0 = c * 32;
        uint32_t dstb = sb + st * A_BUF + (uint32_t)(tid >> 3) * A_STRIDE + (tid & 7) * 16;
        #pragma unroll
        for (int i = 0; i < 4; i++) {
            int t = tok[i];
            const float* src = g_xt + (size_t)(t >= 0 ? t : 0) * DM + k0 + akq;
            cp16(dstb + (uint32_t)(32 * i) * A_STRIDE, src, t >= 0 ? 16 : 0);
        }
    };
    auto ldgB = [&](int k0) {
        #pragma unroll
        for (int h = 0; h < 2; h++)
            #pragma unroll
            for (int i = 0; i < 4; i++) {
                int kk = wid + 8 * i;
                regB[h][i] = *(const float4*)(Wb + (size_t)(k0 + kk) * DFF + n0 + h * 128 + lane * 4);
            }
    };
    auto stsB = [&](int st) {
        char* Bb = smem + 2 * A_BUF + st * BP_BUF;
        #pragma unroll
        for (int h = 0; h < 2; h++) {
            char* Bh = Bb + h * 16384;
            #pragma unroll
            for (int i = 0; i < 4; i++) {
                uint4 t = cvt4(regB[h][i]);
                char* base = Bh + i * 4096;
                *(uint32_t*)(base + boff[0]) = t.x;
                *(uint32_t*)(base + boff[1]) = t.y;
                *(uint32_t*)(base + boff[2]) = t.z;
                *(uint32_t*)(base + boff[3]) = t.w;
            }
        }
    };
    int arow = wm * 64 + (lane & 7) + ((lane >> 3) & 1) * 8;
    int agr  = (lane >> 4);
    int wn = wh & 1;
    int fr = q ^ (wn << 1) ^ (g >> 2);
    uint32_t bthr = (uint32_t)((wh >> 1) * 16384 + (wn * 32 + q * 8 + g) * 64);
    auto compute = [&](int st) {
        uint32_t Abase = sb + st * A_BUF;
        uint32_t Bbase = sb + 2 * A_BUF + st * BP_BUF + bthr;
        #pragma unroll
        for (int ks = 0; ks < 4; ks++) {
            uint32_t af[4][4];
            #pragma unroll
            for (int mf = 0; mf < 4; mf++)
                ldsm4(af[mf], Abase + (arow + mf * 16) * A_STRIDE + (agr + 2 * ks) * 16);
            uint32_t bw[16];
            uint32_t kb2 = Bbase + ks * 4096;
            #pragma unroll
            for (int v = 0; v < 4; v++)
                lds128(&bw[v * 4], kb2 + (uint32_t)(((v ^ fr) & 3) << 4));
            #pragma unroll
            for (int nf = 0; nf < 8; nf++)
                #pragma unroll
                for (int mf = 0; mf < 4; mf++)
                    mma8(acc[mf][nf], af[mf], &bw[nf * 2]);
        }
    };

    ldgB(0); cpA(0); cp_commit(); stsB(0); cp_wait0(); __syncthreads();
    #pragma unroll 1
    for (int c = 0; c < 16; c++) {
        if (c + 1 < 16) { ldgB((c + 1) * 32); cpA(c + 1); cp_commit(); }
        compute(c & 1);
        if (c + 1 < 16) { stsB((c + 1) & 1); cp_wait0(); __syncthreads(); }
    }

    const float* b1e = b1 + (size_t)e * DFF + n0;
    #pragma unroll
    for (int nf = 0; nf < 8; nf++) {
        int col = wh * 64 + nf * 8 + 2 * q;
        float2 bb = *(const float2*)(b1e + col);
        #pragma unroll
        for (int mf = 0; mf < 4; mf++) {
            int r0 = mt * 128 + wm * 64 + mf * 16 + g;
            float* p0 = g_H + ((size_t)e * CAPP + r0) * DFF + n0 + col;
            float2 o0 = make_float2(gelu_t(acc[mf][nf][0] + bb.x),
                                    gelu_t(acc[mf][nf][1] + bb.y));
            *(float2*)p0 = o0;
            float2 o1 = make_float2(gelu_t(acc[mf][nf][2] + bb.x),
                                    gelu_t(acc[mf][nf][3] + bb.y));
            *(float2*)(p0 + 8 * DFF) = o1;
        }
    }
}

// ---------------- 4) GEMM2: Y = H @ W2 + b2 ----------------------------------
// CTA tile 128m x 256n, warp tile 64x64
__global__ __launch_bounds__(256) void hw2_kernel(
        const float* __restrict__ W2, const float* __restrict__ b2) {
    extern __shared__ char smem[];
    uint32_t sb = smem_u32(smem);
    int tid = threadIdx.x, lane = tid & 31, wid = tid >> 5;
    int wm = wid & 1, wh = wid >> 1;
    int g = lane >> 2, q = lane & 3;
    int n0 = blockIdx.x * 256, mt = blockIdx.y, e = blockIdx.z;

    const float* Ab0 = g_H + ((size_t)e * CAPP + mt * 128) * DFF;
    const float* Wb  = W2 + (size_t)e * DFF * DM;

    float acc[4][8][4];
    #pragma unroll
    for (int mf = 0; mf < 4; mf++)
        #pragma unroll
        for (int nf = 0; nf < 8; nf++)
            #pragma unroll
            for (int j = 0; j < 4; j++) acc[mf][nf][j] = 0.f;

    float4 regB[2][4];
    int akq = (tid & 7) * 4;

    int qw = wid & 3, kbw = (wid >> 2) & 1;
    uint32_t boff[4];
    #pragma unroll
    for (int j = 0; j < 4; j++) {
        int n = lane * 4 + j;
        int wnn = n >> 6, nf = (n >> 3) & 7, gg = n & 7;
        int w = nf * 2 + kbw, vv = w >> 2;
        int ff = qw ^ (wnn << 1) ^ (gg >> 2);
        boff[j] = (uint32_t)(((wnn * 32 + qw * 8 + gg) * 16 + ((vv ^ ff) << 2) + (w & 3)) * 4);
    }

    auto cpA = [&](int c) {
        int st = c & 1, k0 = c * 32;
        uint32_t dstb = sb + st * A_BUF + (uint32_t)(tid >> 3) * A_STRIDE + (tid & 7) * 16;
        const float* srcb = Ab0 + (size_t)(tid >> 3) * DFF + k0 + akq;
        #pragma unroll
        for (int i = 0; i < 4; i++)
            cp16(dstb + (uint32_t)(32 * i) * A_STRIDE, srcb + (size_t)(32 * i) * DFF, 16);
    };
    auto ldgB = [&](int k0) {
        #pragma unroll
        for (int h = 0; h < 2; h++)
            #pragma unroll
            for (int i = 0; i < 4; i++) {
                int kk = wid + 8 * i;
                regB[h][i] = *(const float4*)(Wb + (size_t)(k0 + kk) * DM + n0 + h * 128 + lane * 4);
            }
    };
    auto stsB = [&](int st) {
        char* Bb = smem + 2 * A_BUF + st * BP_BUF;
        #pragma unroll
        for (int h = 0; h < 2; h++) {
            char* Bh = Bb + h * 16384;
            #pragma unroll
            for (int i = 0; i < 4; i++) {
                uint4 t = cvt4(regB[h][i]);
                char* base = Bh + i * 4096;
                *(uint32_t*)(base + boff[0]) = t.x;
                *(uint32_t*)(base + boff[1]) = t.y;
                *(uint32_t*)(base + boff[2]) = t.z;
                *(uint32_t*)(base + boff[3]) = t.w;
            }
        }
    };
    int arow = wm * 64 + (lane & 7) + ((lane >> 3) & 1) * 8;
    int agr  = (lane >> 4);
    int wn = wh & 1;
    int fr = q ^ (wn << 1) ^ (g >> 2);
    uint32_t bthr = (uint32_t)((wh >> 1) * 16384 + (wn * 32 + q * 8 + g) * 64);
    auto compute = [&](int st) {
        uint32_t Abase = sb + st * A_BUF;
        uint32_t Bbase = sb + 2 * A_BUF + st * BP_BUF + bthr;
        #pragma unroll
        for (int ks = 0; ks < 4; ks++) {
            uint32_t af[4][4];
            #pragma unroll
            for (int mf = 0; mf < 4; mf++)
                ldsm4(af[mf], Abase + (arow + mf * 16) * A_STRIDE + (agr + 2 * ks) * 16);
            uint32_t bw[16];
            uint32_t kb2 = Bbase + ks * 4096;
            #pragma unroll
            for (int v = 0; v < 4; v++)
                lds128(&bw[v * 4], kb2 + (uint32_t)(((v ^ fr) & 3) << 4));
            #pragma unroll
            for (int nf = 0; nf < 8; nf++)
                #pragma unroll
                for (int mf = 0; mf < 4; mf++)
                    mma8(acc[mf][nf], af[mf], &bw[nf * 2]);
        }
    };

    ldgB(0); cpA(0); cp_commit(); stsB(0); cp_wait0(); __syncthreads();
    #pragma unroll 1
    for (int c = 0; c < 64; c++) {
        if (c + 1 < 64) { ldgB((c + 1) * 32); cpA(c + 1); cp_commit(); }
        compute(c & 1);
        if (c + 1 < 64) { stsB((c + 1) & 1); cp_wait0(); __syncthreads(); }
    }

    const float* b2e = b2 + (size_t)e * DM + n0;
    #pragma unroll
    for (int nf = 0; nf < 8; nf++) {
        int col = wh * 64 + nf * 8 + 2 * q;
        float2 bb = *(const float2*)(b2e + col);
        #pragma unroll
        for (int mf = 0; mf < 4; mf++) {
            int r0 = mt * 128 + wm * 64 + mf * 16 + g;
            float* p0 = g_Y + ((size_t)e * CAPP + r0) * DM + n0 + col;
            float2 o0 = make_float2(acc[mf][nf][0] + bb.x, acc[mf][nf][1] + bb.y);
            *(float2*)p0 = o0;
            float2 o1 = make_float2(acc[mf][nf][2] + bb.x, acc[mf][nf][3] + bb.y);
            *(float2*)(p0 + 8 * DM) = o1;
        }
    }
}

// ---------------- 5) output gather + mean ------------------------------------
__global__ void out_kernel(float* __restrict__ out) {
    int idx = blockIdx.x * blockDim.x + threadIdx.x;
    if (idx >= T_TOK * DM / 4) return;
    int t  = idx / (DM / 4);
    int d4 = (idx % (DM / 4)) * 4;
    int s0 = g_entry_slot[2 * t];
    int s1 = g_entry_slot[2 * t + 1];
    float4 r = make_float4(0.f, 0.f, 0.f, 0.f);
    if (s0 >= 0) {
        float4 v = *(const float4*)(g_Y + (size_t)s0 * DM + d4);
        r.x += v.x; r.y += v.y; r.z += v.z; r.w += v.w;
    }
    if (s1 >= 0) {
        float4 v = *(const float4*)(g_Y + (size_t)s1 * DM + d4);
        r.x += v.x; r.y += v.y; r.z += v.z; r.w += v.w;
    }
    r.x *= 0.5f; r.y *= 0.5f; r.z *= 0.5f; r.w *= 0.5f;
    *(float4*)(out + (size_t)idx * 4) = r;
}

// ---------------- launch -----------------------------------------------------
extern "C" void kernel_launch(void* const* d_in, const int* in_sizes, int n_in,
                              void* d_out, int out_size) {
    const float* x   = (const float*)d_in[0];
    const float* Wh  = (const float*)d_in[1];
    const float* W1  = (const float*)d_in[2];
    const float* b1  = (const float*)d_in[3];
    const float* W2  = (const float*)d_in[4];
    const float* b2  = (const float*)d_in[5];
    float* out = (float*)d_out;

    cudaFuncSetAttribute(xw1_kernel, cudaFuncAttributeMaxDynamicSharedMemorySize, SMEM_TOT);
    cudaFuncSetAttribute(hw2_kernel, cudaFuncAttributeMaxDynamicSharedMemorySize, SMEM_TOT);

    route_kernel<<<T_TOK / 8, 256>>>(x, Wh);
    cvt_x_kernel<<<(T_TOK * DM / 4 + 255) / 256, 256>>>(x);
    rank_kernel<<<1, 1024>>>();
    xw1_kernel<<<dim3(DFF / 256, CAPP / 128, NE), 256, SMEM_TOT>>>(W1, b1);
    hw2_kernel<<<dim3(DM / 256, CAPP / 128, NE), 256, SMEM_TOT>>>(W2, b2);
    out_kernel<<<(T_TOK * DM / 4 + 255) / 256, 256>>>(out);
}

// round 10
// speedup vs baseline: 1.1345x; 1.1345x over previous
#include <cuda_runtime.h>
#include <math.h>
#include <stdint.h>

#define T_TOK 8192
#define DM    512
#define DFF   2048
#define NE    64
#define CAP   320
#define CAPP  384   // padded capacity (3 x 128)

// ---------------- scratch ----------------------------------------------------
__device__ int   g_flat_e[T_TOK * 2];
__device__ int   g_entry_slot[T_TOK * 2];
__device__ int   g_slot_tok[NE * CAPP];
__device__ float g_xt[(size_t)T_TOK * DM];       // x pre-rounded to tf32
__device__ float g_H[(size_t)NE * CAPP * DFF];   // stored tf32-rounded
__device__ float g_Y[(size_t)NE * CAPP * DM];

// ---------------- helpers ----------------------------------------------------
__device__ __forceinline__ uint32_t smem_u32(const void* p) {
    uint32_t a;
    asm("{ .reg .u64 t; cvta.to.shared.u64 t, %1; cvt.u32.u64 %0, t; }"
        : "=r"(a) : "l"(p));
    return a;
}
__device__ __forceinline__ uint32_t cvt_tf32(float f) {
    uint32_t r; asm("cvt.rna.tf32.f32 %0, %1;" : "=r"(r) : "f"(f)); return r;
}
__device__ __forceinline__ uint4 cvt4(float4 v) {
    uint4 t;
    t.x = cvt_tf32(v.x); t.y = cvt_tf32(v.y);
    t.z = cvt_tf32(v.z); t.w = cvt_tf32(v.w);
    return t;
}
__device__ __forceinline__ void ldsm4(uint32_t* r, uint32_t addr) {
    asm volatile("ldmatrix.sync.aligned.m8n8.x4.shared.b16 {%0,%1,%2,%3}, [%4];"
                 : "=r"(r[0]), "=r"(r[1]), "=r"(r[2]), "=r"(r[3]) : "r"(addr));
}
__device__ __forceinline__ void lds128(uint32_t* r, uint32_t addr) {
    asm volatile("ld.shared.v4.b32 {%0,%1,%2,%3}, [%4];"
                 : "=r"(r[0]), "=r"(r[1]), "=r"(r[2]), "=r"(r[3]) : "r"(addr));
}
__device__ __forceinline__ void cp16(uint32_t dst, const void* src, int srcsize) {
    asm volatile("cp.async.cg.shared.global [%0], [%1], 16, %2;"
                 :: "r"(dst), "l"(src), "r"(srcsize));
}
__device__ __forceinline__ void cp_commit() {
    asm volatile("cp.async.commit_group;" ::: "memory");
}
__device__ __forceinline__ void cp_wait0() {
    asm volatile("cp.async.wait_group 0;" ::: "memory");
}
__device__ __forceinline__ void mma8(float* d, const uint32_t* a, const uint32_t* b) {
    asm volatile("mma.sync.aligned.m16n8k8.row.col.f32.tf32.tf32.f32 "
                 "{%0,%1,%2,%3}, {%4,%5,%6,%7}, {%8,%9}, {%0,%1,%2,%3};"
                 : "+f"(d[0]), "+f"(d[1]), "+f"(d[2]), "+f"(d[3])
                 : "r"(a[0]), "r"(a[1]), "r"(a[2]), "r"(a[3]),
                   "r"(b[0]), "r"(b[1]));
}
__device__ __forceinline__ float gelu_f(float h) {
    return 0.5f * h * (1.0f + erff(h * 0.70710678118654752f));
}
__device__ __forceinline__ float gelu_t(float h) {   // gelu rounded to tf32
    return __uint_as_float(cvt_tf32(gelu_f(h)));
}

// smem geometry (bytes)
#define A_STRIDE 144                        // 32 k-floats + 4 pad
#define A_BUF    (128 * A_STRIDE)           // 18432
#define BP_BUF   16384                      // permuted B: 4096 words
#define SMEM_TOT (2 * A_BUF + 2 * BP_BUF)   // 69632

// ---------------- 0) pre-round x to tf32 -------------------------------------
__global__ void cvt_x_kernel(const float* __restrict__ x) {
    int idx = blockIdx.x * blockDim.x + threadIdx.x;
    if (idx >= T_TOK * DM / 4) return;
    float4 v = *(const float4*)(x + (size_t)idx * 4);
    uint4 t = cvt4(v);
    *(uint4*)(g_xt + (size_t)idx * 4) = t;
}

// ---------------- 1) routing -------------------------------------------------
__global__ void route_kernel(const float* __restrict__ x,
                             const float* __restrict__ Wh) {
    int gw   = (blockIdx.x * blockDim.x + threadIdx.x) >> 5;
    int lane = threadIdx.x & 31;
    if (gw >= T_TOK) return;
    const float* xr = x + (size_t)gw * DM;
    float d0 = 0.f, d1 = 0.f;
    #pragma unroll
    for (int j = lane; j < DM; j += 32) {
        float v = xr[j];
        d0 = fmaf(v, Wh[j],      d0);
        d1 = fmaf(v, Wh[DM + j], d1);
    }
    #pragma unroll
    for (int o = 16; o > 0; o >>= 1) {
        d0 += __shfl_down_sync(0xffffffffu, d0, o);
        d1 += __shfl_down_sync(0xffffffffu, d1, o);
    }
    if (lane == 0) {
        g_flat_e[2 * gw]     = ((int)floorf(d0 * 8.0f)) & 63;
        g_flat_e[2 * gw + 1] = ((int)floorf(d1 * 8.0f)) & 63;
    }
}

// ---------------- 2) order-preserving rank -----------------------------------
__global__ void rank_kernel() {
    __shared__ int counts[NE];
    __shared__ int whist[32][NE];
    __shared__ int wpref[32][NE];
    __shared__ int ttot[NE];
    int tid  = threadIdx.x;
    int w    = tid >> 5;
    int lane = tid & 31;
    unsigned lmask = (1u << lane) - 1u;

    if (tid < NE) counts[tid] = 0;
    for (int j = tid; j < NE * CAPP; j += 1024) g_slot_tok[j] = -1;
    __syncthreads();

    for (int tile = 0; tile < (T_TOK * 2) / 1024; tile++) {
        for (int j = tid; j < 32 * NE; j += 1024) (&whist[0][0])[j] = 0;
        __syncthreads();

        int i = tile * 1024 + tid;
        int e = g_flat_e[i];
        unsigned m  = __match_any_sync(0xffffffffu, e);
        int prior   = __popc(m & lmask);
        if ((m & lmask) == 0) whist[w][e] = __popc(m);
        __syncthreads();

        if (tid < NE) {
            int s = 0;
            #pragma unroll
            for (int ww = 0; ww < 32; ww++) { wpref[ww][tid] = s; s += whist[ww][tid]; }
            ttot[tid] = s;
        }
        __syncthreads();

        int pos = counts[e] + wpref[w][e] + prior;
        if (pos < CAP) {
            g_entry_slot[i]            = e * CAPP + pos;
            g_slot_tok[e * CAPP + pos] = i >> 1;
        } else {
            g_entry_slot[i] = -1;
        }
        __syncthreads();
        if (tid < NE) counts[tid] += ttot[tid];
        __syncthreads();
    }
}

// Permuted-B addressing (unchanged):
//  f = q ^ (wn<<1) ^ (g>>2); word = ((ks*2+wn)*32 + q*8+g)*16 + ((v^f)<<2) + (w&3)

// ---------------- 3) GEMM1: H = gelu(gather(x_t) @ W1 + b1) ------------------
// CTA tile 128m x 128n, 4 warps as 2m x 2n, warp tile 64x64 (MF=4, NF=8)
__global__ __launch_bounds__(128) void xw1_kernel(
        const float* __restrict__ W1, const float* __restrict__ b1) {
    extern __shared__ char smem[];
    uint32_t sb = smem_u32(smem);
    int tid = threadIdx.x, lane = tid & 31, wid = tid >> 5;   // 4 warps
    int wm = wid >> 1, wn = wid & 1;
    int g = lane >> 2, q = lane & 3;
    int n0 = blockIdx.x * 128, mt = blockIdx.y, e = blockIdx.z;

    const float* Wb = W1 + (size_t)e * DM * DFF;

    int tok[8];
    #pragma unroll
    for (int i = 0; i < 8; i++)
        tok[i] = g_slot_tok[e * CAPP + mt * 128 + (tid >> 3) + 16 * i];

    float acc[4][8][4];
    #pragma unroll
    for (int mf = 0; mf < 4; mf++)
        #pragma unroll
        for (int nf = 0; nf < 8; nf++)
            #pragma unroll
            for (int j = 0; j < 4; j++) acc[mf][nf][j] = 0.f;

    float4 regB[8];
    int akq = (tid & 7) * 4;

    // B writer: q = wid (const per warp); kb = i&1, ks = i>>1
    uint32_t boff[2][4];
    #pragma unroll
    for (int kb = 0; kb < 2; kb++)
        #pragma unroll
        for (int j = 0; j < 4; j++) {
            int n = lane * 4 + j;
            int wnn = n >> 6, nf = (n >> 3) & 7, gg = n & 7;
            int w = nf * 2 + kb, vv = w >> 2;
            int ff = wid ^ (wnn << 1) ^ (gg >> 2);
            boff[kb][j] = (uint32_t)(((wnn * 32 + wid * 8 + gg) * 16 + ((vv ^ ff) << 2) + (w & 3)) * 4);
        }

    auto cpA = [&](int c) {
        int st = c & 1, k0 = c * 32;
        uint32_t dstb = sb + st * A_BUF + (uint32_t)(tid >> 3) * A_STRIDE + (tid & 7) * 16;
        #pragma unroll
        for (int i = 0; i < 8; i++) {
            int t = tok[i];
            const float* src = g_xt + (size_t)(t >= 0 ? t : 0) * DM + k0 + akq;
            cp16(dstb + (uint32_t)(16 * i) * A_STRIDE, src, t >= 0 ? 16 : 0);
        }
    };
    auto ldgB = [&](int k0) {
        #pragma unroll
        for (int i = 0; i < 8; i++) {
            int kk = wid + 4 * i;
            regB[i] = *(const float4*)(Wb + (size_t)(k0 + kk) * DFF + n0 + lane * 4);
        }
    };
    auto stsB = [&](int st) {
        char* Bb = smem + 2 * A_BUF + st * BP_BUF;
        #pragma unroll
        for (int i = 0; i < 8; i++) {
            uint4 t = cvt4(regB[i]);
            char* base = Bb + (i >> 1) * 4096;
            const uint32_t* bo = boff[i & 1];
            *(uint32_t*)(base + bo[0]) = t.x;
            *(uint32_t*)(base + bo[1]) = t.y;
            *(uint32_t*)(base + bo[2]) = t.z;
            *(uint32_t*)(base + bo[3]) = t.w;
        }
    };
    int arow = wm * 64 + (lane & 7) + ((lane >> 3) & 1) * 8;
    int agr  = (lane >> 4);
    int fr = q ^ (wn << 1) ^ (g >> 2);
    uint32_t bthr = (uint32_t)((wn * 32 + q * 8 + g) * 64);
    auto compute = [&](int st) {
        uint32_t Abase = sb + st * A_BUF;
        uint32_t Bbase = sb + 2 * A_BUF + st * BP_BUF + bthr;
        #pragma unroll
        for (int ks = 0; ks < 4; ks++) {
            uint32_t af[4][4];
            #pragma unroll
            for (int mf = 0; mf < 4; mf++)
                ldsm4(af[mf], Abase + (arow + mf * 16) * A_STRIDE + (agr + 2 * ks) * 16);
            uint32_t bw[16];
            uint32_t kb2 = Bbase + ks * 4096;
            #pragma unroll
            for (int v = 0; v < 4; v++)
                lds128(&bw[v * 4], kb2 + (uint32_t)(((v ^ fr) & 3) << 4));
            #pragma unroll
            for (int nf = 0; nf < 8; nf++)
                #pragma unroll
                for (int mf = 0; mf < 4; mf++)
                    mma8(acc[mf][nf], af[mf], &bw[nf * 2]);
        }
    };

    ldgB(0); cpA(0); cp_commit(); stsB(0); cp_wait0(); __syncthreads();
    #pragma unroll 1
    for (int c = 0; c < 16; c++) {
        if (c + 1 < 16) { ldgB((c + 1) * 32); cpA(c + 1); cp_commit(); }
        compute(c & 1);
        if (c + 1 < 16) { stsB((c + 1) & 1); cp_wait0(); __syncthreads(); }
    }

    const float* b1e = b1 + (size_t)e * DFF + n0;
    #pragma unroll
    for (int nf = 0; nf < 8; nf++) {
        int col = wn * 64 + nf * 8 + 2 * q;
        float2 bb = *(const float2*)(b1e + col);
        #pragma unroll
        for (int mf = 0; mf < 4; mf++) {
            int r0 = mt * 128 + wm * 64 + mf * 16 + g;
            float* p0 = g_H + ((size_t)e * CAPP + r0) * DFF + n0 + col;
            float2 o0 = make_float2(gelu_t(acc[mf][nf][0] + bb.x),
                                    gelu_t(acc[mf][nf][1] + bb.y));
            *(float2*)p0 = o0;
            float2 o1 = make_float2(gelu_t(acc[mf][nf][2] + bb.x),
                                    gelu_t(acc[mf][nf][3] + bb.y));
            *(float2*)(p0 + 8 * DFF) = o1;
        }
    }
}

// ---------------- 4) GEMM2: Y = H @ W2 + b2 ----------------------------------
// CTA tile 128m x 128n, 4 warps, warp tile 64x64
__global__ __launch_bounds__(128) void hw2_kernel(
        const float* __restrict__ W2, const float* __restrict__ b2) {
    extern __shared__ char smem[];
    uint32_t sb = smem_u32(smem);
    int tid = threadIdx.x, lane = tid & 31, wid = tid >> 5;
    int wm = wid >> 1, wn = wid & 1;
    int g = lane >> 2, q = lane & 3;
    int n0 = blockIdx.x * 128, mt = blockIdx.y, e = blockIdx.z;

    const float* Ab0 = g_H + ((size_t)e * CAPP + mt * 128) * DFF;
    const float* Wb  = W2 + (size_t)e * DFF * DM;

    float acc[4][8][4];
    #pragma unroll
    for (int mf = 0; mf < 4; mf++)
        #pragma unroll
        for (int nf = 0; nf < 8; nf++)
            #pragma unroll
            for (int j = 0; j < 4; j++) acc[mf][nf][j] = 0.f;

    float4 regB[8];
    int akq = (tid & 7) * 4;

    uint32_t boff[2][4];
    #pragma unroll
    for (int kb = 0; kb < 2; kb++)
        #pragma unroll
        for (int j = 0; j < 4; j++) {
            int n = lane * 4 + j;
            int wnn = n >> 6, nf = (n >> 3) & 7, gg = n & 7;
            int w = nf * 2 + kb, vv = w >> 2;
            int ff = wid ^ (wnn << 1) ^ (gg >> 2);
            boff[kb][j] = (uint32_t)(((wnn * 32 + wid * 8 + gg) * 16 + ((vv ^ ff) << 2) + (w & 3)) * 4);
        }

    auto cpA = [&](int c) {
        int st = c & 1, k0 = c * 32;
        uint32_t dstb = sb + st * A_BUF + (uint32_t)(tid >> 3) * A_STRIDE + (tid & 7) * 16;
        const float* srcb = Ab0 + (size_t)(tid >> 3) * DFF + k0 + akq;
        #pragma unroll
        for (int i = 0; i < 8; i++)
            cp16(dstb + (uint32_t)(16 * i) * A_STRIDE, srcb + (size_t)(16 * i) * DFF, 16);
    };
    auto ldgB = [&](int k0) {
        #pragma unroll
        for (int i = 0; i < 8; i++) {
            int kk = wid + 4 * i;
            regB[i] = *(const float4*)(Wb + (size_t)(k0 + kk) * DM + n0 + lane * 4);
        }
    };
    auto stsB = [&](int st) {
        char* Bb = smem + 2 * A_BUF + st * BP_BUF;
        #pragma unroll
        for (int i = 0; i < 8; i++) {
            uint4 t = cvt4(regB[i]);
            char* base = Bb + (i >> 1) * 4096;
            const uint32_t* bo = boff[i & 1];
            *(uint32_t*)(base + bo[0]) = t.x;
            *(uint32_t*)(base + bo[1]) = t.y;
            *(uint32_t*)(base + bo[2]) = t.z;
            *(uint32_t*)(base + bo[3]) = t.w;
        }
    };
    int arow = wm * 64 + (lane & 7) + ((lane >> 3) & 1) * 8;
    int agr  = (lane >> 4);
    int fr = q ^ (wn << 1) ^ (g >> 2);
    uint32_t bthr = (uint32_t)((wn * 32 + q * 8 + g) * 64);
    auto compute = [&](int st) {
        uint32_t Abase = sb + st * A_BUF;
        uint32_t Bbase = sb + 2 * A_BUF + st * BP_BUF + bthr;
        #pragma unroll
        for (int ks = 0; ks < 4; ks++) {
            uint32_t af[4][4];
            #pragma unroll
            for (int mf = 0; mf < 4; mf++)
                ldsm4(af[mf], Abase + (arow + mf * 16) * A_STRIDE + (agr + 2 * ks) * 16);
            uint32_t bw[16];
            uint32_t kb2 = Bbase + ks * 4096;
            #pragma unroll
            for (int v = 0; v < 4; v++)
                lds128(&bw[v * 4], kb2 + (uint32_t)(((v ^ fr) & 3) << 4));
            #pragma unroll
            for (int nf = 0; nf < 8; nf++)
                #pragma unroll
                for (int mf = 0; mf < 4; mf++)
                    mma8(acc[mf][nf], af[mf], &bw[nf * 2]);
        }
    };

    ldgB(0); cpA(0); cp_commit(); stsB(0); cp_wait0(); __syncthreads();
    #pragma unroll 1
    for (int c = 0; c < 64; c++) {
        if (c + 1 < 64) { ldgB((c + 1) * 32); cpA(c + 1); cp_commit(); }
        compute(c & 1);
        if (c + 1 < 64) { stsB((c + 1) & 1); cp_wait0(); __syncthreads(); }
    }

    const float* b2e = b2 + (size_t)e * DM + n0;
    #pragma unroll
    for (int nf = 0; nf < 8; nf++) {
        int col = wn * 64 + nf * 8 + 2 * q;
        float2 bb = *(const float2*)(b2e + col);
        #pragma unroll
        for (int mf = 0; mf < 4; mf++) {
            int r0 = mt * 128 + wm * 64 + mf * 16 + g;
            float* p0 = g_Y + ((size_t)e * CAPP + r0) * DM + n0 + col;
            float2 o0 = make_float2(acc[mf][nf][0] + bb.x, acc[mf][nf][1] + bb.y);
            *(float2*)p0 = o0;
            float2 o1 = make_float2(acc[mf][nf][2] + bb.x, acc[mf][nf][3] + bb.y);
            *(float2*)(p0 + 8 * DM) = o1;
        }
    }
}

// ---------------- 5) output gather + mean ------------------------------------
__global__ void out_kernel(float* __restrict__ out) {
    int idx = blockIdx.x * blockDim.x + threadIdx.x;
    if (idx >= T_TOK * DM / 4) return;
    int t  = idx / (DM / 4);
    int d4 = (idx % (DM / 4)) * 4;
    int s0 = g_entry_slot[2 * t];
    int s1 = g_entry_slot[2 * t + 1];
    float4 r = make_float4(0.f, 0.f, 0.f, 0.f);
    if (s0 >= 0) {
        float4 v = *(const float4*)(g_Y + (size_t)s0 * DM + d4);
        r.x += v.x; r.y += v.y; r.z += v.z; r.w += v.w;
    }
    if (s1 >= 0) {
        float4 v = *(const float4*)(g_Y + (size_t)s1 * DM + d4);
        r.x += v.x; r.y += v.y; r.z += v.z; r.w += v.w;
    }
    r.x *= 0.5f; r.y *= 0.5f; r.z *= 0.5f; r.w *= 0.5f;
    *(float4*)(out + (size_t)idx * 4) = r;
}

// ---------------- launch -----------------------------------------------------
extern "C" void kernel_launch(void* const* d_in, const int* in_sizes, int n_in,
                              void* d_out, int out_size) {
    const float* x   = (const float*)d_in[0];
    const float* Wh  = (const float*)d_in[1];
    const float* W1  = (const float*)d_in[2];
    const float* b1  = (const float*)d_in[3];
    const float* W2  = (const float*)d_in[4];
    const float* b2  = (const float*)d_in[5];
    float* out = (float*)d_out;

    cudaFuncSetAttribute(xw1_kernel, cudaFuncAttributeMaxDynamicSharedMemorySize, SMEM_TOT);
    cudaFuncSetAttribute(hw2_kernel, cudaFuncAttributeMaxDynamicSharedMemorySize, SMEM_TOT);

    route_kernel<<<T_TOK / 8, 256>>>(x, Wh);
    cvt_x_kernel<<<(T_TOK * DM / 4 + 255) / 256, 256>>>(x);
    rank_kernel<<<1, 1024>>>();
    xw1_kernel<<<dim3(DFF / 128, CAPP / 128, NE), 128, SMEM_TOT>>>(W1, b1);
    hw2_kernel<<<dim3(DM / 128, CAPP / 128, NE), 128, SMEM_TOT>>>(W2, b2);
    out_kernel<<<(T_TOK * DM / 4 + 255) / 256, 256>>>(out);
}

// round 11
// speedup vs baseline: 1.7109x; 1.5081x over previous
#include <cuda_runtime.h>
#include <math.h>
#include <stdint.h>

#define T_TOK 8192
#define DM    512
#define DFF   2048
#define NE    64
#define CAP   320
#define CAPP  384   // padded capacity (3 x 128)

// ---------------- scratch ----------------------------------------------------
__device__ int   g_flat_e[T_TOK * 2];
__device__ int   g_entry_slot[T_TOK * 2];
__device__ int   g_slot_tok[NE * CAPP];
__device__ int   g_cnt[NE];                      // raw per-expert entry count
__device__ float g_xt[(size_t)T_TOK * DM];       // x pre-rounded to tf32
__device__ float g_H[(size_t)NE * CAPP * DFF];   // stored tf32-rounded
__device__ float g_Y[(size_t)NE * CAPP * DM];

// ---------------- helpers ----------------------------------------------------
__device__ __forceinline__ uint32_t smem_u32(const void* p) {
    uint32_t a;
    asm("{ .reg .u64 t; cvta.to.shared.u64 t, %1; cvt.u32.u64 %0, t; }"
        : "=r"(a) : "l"(p));
    return a;
}
__device__ __forceinline__ uint32_t cvt_tf32(float f) {
    uint32_t r; asm("cvt.rna.tf32.f32 %0, %1;" : "=r"(r) : "f"(f)); return r;
}
__device__ __forceinline__ uint4 cvt4(float4 v) {
    uint4 t;
    t.x = cvt_tf32(v.x); t.y = cvt_tf32(v.y);
    t.z = cvt_tf32(v.z); t.w = cvt_tf32(v.w);
    return t;
}
__device__ __forceinline__ void ldsm4(uint32_t* r, uint32_t addr) {
    asm volatile("ldmatrix.sync.aligned.m8n8.x4.shared.b16 {%0,%1,%2,%3}, [%4];"
                 : "=r"(r[0]), "=r"(r[1]), "=r"(r[2]), "=r"(r[3]) : "r"(addr));
}
__device__ __forceinline__ void lds128(uint32_t* r, uint32_t addr) {
    asm volatile("ld.shared.v4.b32 {%0,%1,%2,%3}, [%4];"
                 : "=r"(r[0]), "=r"(r[1]), "=r"(r[2]), "=r"(r[3]) : "r"(addr));
}
__device__ __forceinline__ void cp16(uint32_t dst, const void* src, int srcsize) {
    asm volatile("cp.async.cg.shared.global [%0], [%1], 16, %2;"
                 :: "r"(dst), "l"(src), "r"(srcsize));
}
__device__ __forceinline__ void cp_commit() {
    asm volatile("cp.async.commit_group;" ::: "memory");
}
__device__ __forceinline__ void cp_wait0() {
    asm volatile("cp.async.wait_group 0;" ::: "memory");
}
__device__ __forceinline__ void mma8(float* d, const uint32_t* a, const uint32_t* b) {
    asm volatile("mma.sync.aligned.m16n8k8.row.col.f32.tf32.tf32.f32 "
                 "{%0,%1,%2,%3}, {%4,%5,%6,%7}, {%8,%9}, {%0,%1,%2,%3};"
                 : "+f"(d[0]), "+f"(d[1]), "+f"(d[2]), "+f"(d[3])
                 : "r"(a[0]), "r"(a[1]), "r"(a[2]), "r"(a[3]),
                   "r"(b[0]), "r"(b[1]));
}
__device__ __forceinline__ float gelu_f(float h) {
    return 0.5f * h * (1.0f + erff(h * 0.70710678118654752f));
}
__device__ __forceinline__ float gelu_t(float h) {   // gelu rounded to tf32
    return __uint_as_float(cvt_tf32(gelu_f(h)));
}

// smem geometry (bytes)
#define A_STRIDE 144                        // 32 k-floats + 4 pad
#define A_BUF    (128 * A_STRIDE)           // 18432
#define BP_BUF   16384                      // permuted B: 4096 words
#define SMEM_TOT (2 * A_BUF + 2 * BP_BUF)   // 69632

// ---------------- 0) pre-round x to tf32 -------------------------------------
__global__ void cvt_x_kernel(const float* __restrict__ x) {
    int idx = blockIdx.x * blockDim.x + threadIdx.x;
    if (idx >= T_TOK * DM / 4) return;
    float4 v = *(const float4*)(x + (size_t)idx * 4);
    uint4 t = cvt4(v);
    *(uint4*)(g_xt + (size_t)idx * 4) = t;
}

// ---------------- 1) routing -------------------------------------------------
__global__ void route_kernel(const float* __restrict__ x,
                             const float* __restrict__ Wh) {
    int gw   = (blockIdx.x * blockDim.x + threadIdx.x) >> 5;
    int lane = threadIdx.x & 31;
    if (gw >= T_TOK) return;
    const float* xr = x + (size_t)gw * DM;
    float d0 = 0.f, d1 = 0.f;
    #pragma unroll
    for (int j = lane; j < DM; j += 32) {
        float v = xr[j];
        d0 = fmaf(v, Wh[j],      d0);
        d1 = fmaf(v, Wh[DM + j], d1);
    }
    #pragma unroll
    for (int o = 16; o > 0; o >>= 1) {
        d0 += __shfl_down_sync(0xffffffffu, d0, o);
        d1 += __shfl_down_sync(0xffffffffu, d1, o);
    }
    if (lane == 0) {
        g_flat_e[2 * gw]     = ((int)floorf(d0 * 8.0f)) & 63;
        g_flat_e[2 * gw + 1] = ((int)floorf(d1 * 8.0f)) & 63;
    }
}

// ---------------- 2) order-preserving rank -----------------------------------
__global__ void rank_kernel() {
    __shared__ int counts[NE];
    __shared__ int whist[32][NE];
    __shared__ int wpref[32][NE];
    __shared__ int ttot[NE];
    int tid  = threadIdx.x;
    int w    = tid >> 5;
    int lane = tid & 31;
    unsigned lmask = (1u << lane) - 1u;

    if (tid < NE) counts[tid] = 0;
    for (int j = tid; j < NE * CAPP; j += 1024) g_slot_tok[j] = -1;
    __syncthreads();

    for (int tile = 0; tile < (T_TOK * 2) / 1024; tile++) {
        for (int j = tid; j < 32 * NE; j += 1024) (&whist[0][0])[j] = 0;
        __syncthreads();

        int i = tile * 1024 + tid;
        int e = g_flat_e[i];
        unsigned m  = __match_any_sync(0xffffffffu, e);
        int prior   = __popc(m & lmask);
        if ((m & lmask) == 0) whist[w][e] = __popc(m);
        __syncthreads();

        if (tid < NE) {
            int s = 0;
            #pragma unroll
            for (int ww = 0; ww < 32; ww++) { wpref[ww][tid] = s; s += whist[ww][tid]; }
            ttot[tid] = s;
        }
        __syncthreads();

        int pos = counts[e] + wpref[w][e] + prior;
        if (pos < CAP) {
            g_entry_slot[i]            = e * CAPP + pos;
            g_slot_tok[e * CAPP + pos] = i >> 1;
        } else {
            g_entry_slot[i] = -1;
        }
        __syncthreads();
        if (tid < NE) counts[tid] += ttot[tid];
        __syncthreads();
    }
    if (tid < NE) g_cnt[tid] = counts[tid];   // raw count (may exceed CAP)
}

// Permuted-B addressing (unchanged):
//  f = q ^ (wn<<1) ^ (g>>2); word = ((ks*2+wn)*32 + q*8+g)*16 + ((v^f)<<2) + (w&3)

// ---------------- 3) GEMM1: H = gelu(gather(x_t) @ W1 + b1) ------------------
// CTA tile 128m x 128n, 8 warps as 4m x 2n, warp tile 32x64 (MF=2, NF=8)
__global__ __launch_bounds__(256, 2) void xw1_kernel(
        const float* __restrict__ W1, const float* __restrict__ b1) {
    extern __shared__ char smem[];
    uint32_t sb = smem_u32(smem);
    int tid = threadIdx.x, lane = tid & 31, wid = tid >> 5;
    int wm = wid & 3, wn = wid >> 2;
    int g = lane >> 2, q = lane & 3;
    int n0 = blockIdx.x * 128, mt = blockIdx.y, e = blockIdx.z;

    if (mt * 128 >= g_cnt[e]) return;   // skip pure-padding M tiles

    const float* Wb = W1 + (size_t)e * DM * DFF;

    int tok[4];
    #pragma unroll
    for (int i = 0; i < 4; i++)
        tok[i] = g_slot_tok[e * CAPP + mt * 128 + (tid >> 3) + 32 * i];

    float acc[2][8][4];
    #pragma unroll
    for (int mf = 0; mf < 2; mf++)
        #pragma unroll
        for (int nf = 0; nf < 8; nf++)
            #pragma unroll
            for (int j = 0; j < 4; j++) acc[mf][nf][j] = 0.f;

    float4 regB[4];
    int akq = (tid & 7) * 4;

    int qw = wid & 3, kbw = (wid >> 2) & 1;
    uint32_t boff[4];
    #pragma unroll
    for (int j = 0; j < 4; j++) {
        int n = lane * 4 + j;
        int wnn = n >> 6, nf = (n >> 3) & 7, gg = n & 7;
        int w = nf * 2 + kbw, vv = w >> 2;
        int ff = qw ^ (wnn << 1) ^ (gg >> 2);
        boff[j] = (uint32_t)(((wnn * 32 + qw * 8 + gg) * 16 + ((vv ^ ff) << 2) + (w & 3)) * 4);
    }

    auto cpA = [&](int c) {
        int st = c & 1, k0 = c * 32;
        uint32_t dstb = sb + st * A_BUF + (uint32_t)(tid >> 3) * A_STRIDE + (tid & 7) * 16;
        #pragma unroll
        for (int i = 0; i < 4; i++) {
            int t = tok[i];
            const float* src = g_xt + (size_t)(t >= 0 ? t : 0) * DM + k0 + akq;
            cp16(dstb + (uint32_t)(32 * i) * A_STRIDE, src, t >= 0 ? 16 : 0);
        }
    };
    auto ldgB = [&](int k0) {
        #pragma unroll
        for (int i = 0; i < 4; i++) {
            int kk = wid + 8 * i;
            regB[i] = *(const float4*)(Wb + (size_t)(k0 + kk) * DFF + n0 + lane * 4);
        }
    };
    auto stsB = [&](int st) {
        char* Bb = smem + 2 * A_BUF + st * BP_BUF;
        #pragma unroll
        for (int i = 0; i < 4; i++) {
            uint4 t = cvt4(regB[i]);
            char* base = Bb + i * 4096;
            *(uint32_t*)(base + boff[0]) = t.x;
            *(uint32_t*)(base + boff[1]) = t.y;
            *(uint32_t*)(base + boff[2]) = t.z;
            *(uint32_t*)(base + boff[3]) = t.w;
        }
    };
    int arow = wm * 32 + (lane & 7) + ((lane >> 3) & 1) * 8;
    int agr  = (lane >> 4);
    int wn2 = wn & 1;
    int fr = q ^ (wn2 << 1) ^ (g >> 2);
    uint32_t bthr = (uint32_t)((wn * 32 + q * 8 + g) * 64);
    auto compute = [&](int st) {
        uint32_t Abase = sb + st * A_BUF;
        uint32_t Bbase = sb + 2 * A_BUF + st * BP_BUF + bthr;
        #pragma unroll
        for (int ks = 0; ks < 4; ks++) {
            uint32_t af[2][4];
            ldsm4(af[0], Abase + arow * A_STRIDE + (agr + 2 * ks) * 16);
            ldsm4(af[1], Abase + (arow + 16) * A_STRIDE + (agr + 2 * ks) * 16);
            uint32_t bw[16];
            uint32_t kb2 = Bbase + ks * 4096;
            #pragma unroll
            for (int v = 0; v < 4; v++)
                lds128(&bw[v * 4], kb2 + (uint32_t)(((v ^ fr) & 3) << 4));
            #pragma unroll
            for (int nf = 0; nf < 8; nf++) {
                mma8(acc[0][nf], af[0], &bw[nf * 2]);
                mma8(acc[1][nf], af[1], &bw[nf * 2]);
            }
        }
    };

    ldgB(0); cpA(0); cp_commit(); stsB(0); cp_wait0(); __syncthreads();
    #pragma unroll 1
    for (int c = 0; c < 16; c++) {
        if (c + 1 < 16) { ldgB((c + 1) * 32); cpA(c + 1); cp_commit(); }
        compute(c & 1);
        if (c + 1 < 16) { stsB((c + 1) & 1); cp_wait0(); __syncthreads(); }
    }

    const float* b1e = b1 + (size_t)e * DFF + n0;
    #pragma unroll
    for (int nf = 0; nf < 8; nf++) {
        int col = wn * 64 + nf * 8 + 2 * q;
        float2 bb = *(const float2*)(b1e + col);
        #pragma unroll
        for (int mf = 0; mf < 2; mf++) {
            int r0 = mt * 128 + wm * 32 + mf * 16 + g;
            float* p0 = g_H + ((size_t)e * CAPP + r0) * DFF + n0 + col;
            float2 o0 = make_float2(gelu_t(acc[mf][nf][0] + bb.x),
                                    gelu_t(acc[mf][nf][1] + bb.y));
            *(float2*)p0 = o0;
            float2 o1 = make_float2(gelu_t(acc[mf][nf][2] + bb.x),
                                    gelu_t(acc[mf][nf][3] + bb.y));
            *(float2*)(p0 + 8 * DFF) = o1;
        }
    }
}

// ---------------- 4) GEMM2: Y = H @ W2 + b2 ----------------------------------
__global__ __launch_bounds__(256, 2) void hw2_kernel(
        const float* __restrict__ W2, const float* __restrict__ b2) {
    extern __shared__ char smem[];
    uint32_t sb = smem_u32(smem);
    int tid = threadIdx.x, lane = tid & 31, wid = tid >> 5;
    int wm = wid & 3, wn = wid >> 2;
    int g = lane >> 2, q = lane & 3;
    int n0 = blockIdx.x * 128, mt = blockIdx.y, e = blockIdx.z;

    if (mt * 128 >= g_cnt[e]) return;   // skip pure-padding M tiles

    const float* Ab0 = g_H + ((size_t)e * CAPP + mt * 128) * DFF;
    const float* Wb  = W2 + (size_t)e * DFF * DM;

    float acc[2][8][4];
    #pragma unroll
    for (int mf = 0; mf < 2; mf++)
        #pragma unroll
        for (int nf = 0; nf < 8; nf++)
            #pragma unroll
            for (int j = 0; j < 4; j++) acc[mf][nf][j] = 0.f;

    float4 regB[4];
    int akq = (tid & 7) * 4;

    int qw = wid & 3, kbw = (wid >> 2) & 1;
    uint32_t boff[4];
    #pragma unroll
    for (int j = 0; j < 4; j++) {
        int n = lane * 4 + j;
        int wnn = n >> 6, nf = (n >> 3) & 7, gg = n & 7;
        int w = nf * 2 + kbw, vv = w >> 2;
        int ff = qw ^ (wnn << 1) ^ (gg >> 2);
        boff[j] = (uint32_t)(((wnn * 32 + qw * 8 + gg) * 16 + ((vv ^ ff) << 2) + (w & 3)) * 4);
    }

    auto cpA = [&](int c) {
        int st = c & 1, k0 = c * 32;
        uint32_t dstb = sb + st * A_BUF + (uint32_t)(tid >> 3) * A_STRIDE + (tid & 7) * 16;
        const float* srcb = Ab0 + (size_t)(tid >> 3) * DFF + k0 + akq;
        #pragma unroll
        for (int i = 0; i < 4; i++)
            cp16(dstb + (uint32_t)(32 * i) * A_STRIDE, srcb + (size_t)(32 * i) * DFF, 16);
    };
    auto ldgB = [&](int k0) {
        #pragma unroll
        for (int i = 0; i < 4; i++) {
            int kk = wid + 8 * i;
            regB[i] = *(const float4*)(Wb + (size_t)(k0 + kk) * DM + n0 + lane * 4);
        }
    };
    auto stsB = [&](int st) {
        char* Bb = smem + 2 * A_BUF + st * BP_BUF;
        #pragma unroll
        for (int i = 0; i < 4; i++) {
            uint4 t = cvt4(regB[i]);
            char* base = Bb + i * 4096;
            *(uint32_t*)(base + boff[0]) = t.x;
            *(uint32_t*)(base + boff[1]) = t.y;
            *(uint32_t*)(base + boff[2]) = t.z;
            *(uint32_t*)(base + boff[3]) = t.w;
        }
    };
    int arow = wm * 32 + (lane & 7) + ((lane >> 3) & 1) * 8;
    int agr  = (lane >> 4);
    int wn2 = wn & 1;
    int fr = q ^ (wn2 << 1) ^ (g >> 2);
    uint32_t bthr = (uint32_t)((wn * 32 + q * 8 + g) * 64);
    auto compute = [&](int st) {
        uint32_t Abase = sb + st * A_BUF;
        uint32_t Bbase = sb + 2 * A_BUF + st * BP_BUF + bthr;
        #pragma unroll
        for (int ks = 0; ks < 4; ks++) {
            uint32_t af[2][4];
            ldsm4(af[0], Abase + arow * A_STRIDE + (agr + 2 * ks) * 16);
            ldsm4(af[1], Abase + (arow + 16) * A_STRIDE + (agr + 2 * ks) * 16);
            uint32_t bw[16];
            uint32_t kb2 = Bbase + ks * 4096;
            #pragma unroll
            for (int v = 0; v < 4; v++)
                lds128(&bw[v * 4], kb2 + (uint32_t)(((v ^ fr) & 3) << 4));
            #pragma unroll
            for (int nf = 0; nf < 8; nf++) {
                mma8(acc[0][nf], af[0], &bw[nf * 2]);
                mma8(acc[1][nf], af[1], &bw[nf * 2]);
            }
        }
    };

    ldgB(0); cpA(0); cp_commit(); stsB(0); cp_wait0(); __syncthreads();
    #pragma unroll 1
    for (int c = 0; c < 64; c++) {
        if (c + 1 < 64) { ldgB((c + 1) * 32); cpA(c + 1); cp_commit(); }
        compute(c & 1);
        if (c + 1 < 64) { stsB((c + 1) & 1); cp_wait0(); __syncthreads(); }
    }

    const float* b2e = b2 + (size_t)e * DM + n0;
    #pragma unroll
    for (int nf = 0; nf < 8; nf++) {
        int col = wn * 64 + nf * 8 + 2 * q;
        float2 bb = *(const float2*)(b2e + col);
        #pragma unroll
        for (int mf = 0; mf < 2; mf++) {
            int r0 = mt * 128 + wm * 32 + mf * 16 + g;
            float* p0 = g_Y + ((size_t)e * CAPP + r0) * DM + n0 + col;
            float2 o0 = make_float2(acc[mf][nf][0] + bb.x, acc[mf][nf][1] + bb.y);
            *(float2*)p0 = o0;
            float2 o1 = make_float2(acc[mf][nf][2] + bb.x, acc[mf][nf][3] + bb.y);
            *(float2*)(p0 + 8 * DM) = o1;
        }
    }
}

// ---------------- 5) output gather + mean ------------------------------------
__global__ void out_kernel(float* __restrict__ out) {
    int idx = blockIdx.x * blockDim.x + threadIdx.x;
    if (idx >= T_TOK * DM / 4) return;
    int t  = idx / (DM / 4);
    int d4 = (idx % (DM / 4)) * 4;
    int s0 = g_entry_slot[2 * t];
    int s1 = g_entry_slot[2 * t + 1];
    float4 r = make_float4(0.f, 0.f, 0.f, 0.f);
    if (s0 >= 0) {
        float4 v = *(const float4*)(g_Y + (size_t)s0 * DM + d4);
        r.x += v.x; r.y += v.y; r.z += v.z; r.w += v.w;
    }
    if (s1 >= 0) {
        float4 v = *(const float4*)(g_Y + (size_t)s1 * DM + d4);
        r.x += v.x; r.y += v.y; r.z += v.z; r.w += v.w;
    }
    r.x *= 0.5f; r.y *= 0.5f; r.z *= 0.5f; r.w *= 0.5f;
    *(float4*)(out + (size_t)idx * 4) = r;
}

// ---------------- launch -----------------------------------------------------
extern "C" void kernel_launch(void* const* d_in, const int* in_sizes, int n_in,
                              void* d_out, int out_size) {
    const float* x   = (const float*)d_in[0];
    const float* Wh  = (const float*)d_in[1];
    const float* W1  = (const float*)d_in[2];
    const float* b1  = (const float*)d_in[3];
    const float* W2  = (const float*)d_in[4];
    const float* b2  = (const float*)d_in[5];
    float* out = (float*)d_out;

    cudaFuncSetAttribute(xw1_kernel, cudaFuncAttributeMaxDynamicSharedMemorySize, SMEM_TOT);
    cudaFuncSetAttribute(hw2_kernel, cudaFuncAttributeMaxDynamicSharedMemorySize, SMEM_TOT);

    route_kernel<<<T_TOK / 8, 256>>>(x, Wh);
    cvt_x_kernel<<<(T_TOK * DM / 4 + 255) / 256, 256>>>(x);
    rank_kernel<<<1, 1024>>>();
    xw1_kernel<<<dim3(DFF / 128, CAPP / 128, NE), 256, SMEM_TOT>>>(W1, b1);
    hw2_kernel<<<dim3(DM / 128, CAPP / 128, NE), 256, SMEM_TOT>>>(W2, b2);
    out_kernel<<<(T_TOK * DM / 4 + 255) / 256, 256>>>(out);
}

// round 12
// speedup vs baseline: 2.5354x; 1.4820x over previous
#include <cuda_runtime.h>
#include <cuda_fp16.h>
#include <math.h>
#include <stdint.h>

#define T_TOK 8192
#define DM    512
#define DFF   2048
#define NE    64
#define CAP   320
#define CAPP  384   // padded capacity (3 x 128)

// ---------------- scratch ----------------------------------------------------
__device__ int    g_flat_e[T_TOK * 2];
__device__ int    g_entry_slot[T_TOK * 2];
__device__ int    g_slot_tok[NE * CAPP];
__device__ int    g_cnt[NE];                       // raw per-expert entry count
__device__ __half g_xh[(size_t)T_TOK * DM];        // x pre-rounded to fp16
__device__ __half g_Hh[(size_t)NE * CAPP * DFF];   // H stored fp16
__device__ float  g_Y[(size_t)NE * CAPP * DM];

// ---------------- helpers ----------------------------------------------------
__device__ __forceinline__ uint32_t smem_u32(const void* p) {
    uint32_t a;
    asm("{ .reg .u64 t; cvta.to.shared.u64 t, %1; cvt.u32.u64 %0, t; }"
        : "=r"(a) : "l"(p));
    return a;
}
__device__ __forceinline__ uint32_t pack_h2(float lo, float hi) {
    uint32_t w;
    asm("cvt.rn.f16x2.f32 %0, %1, %2;" : "=r"(w) : "f"(hi), "f"(lo));
    return w;
}
__device__ __forceinline__ void ldsm4(uint32_t* r, uint32_t addr) {
    asm volatile("ldmatrix.sync.aligned.m8n8.x4.shared.b16 {%0,%1,%2,%3}, [%4];"
                 : "=r"(r[0]), "=r"(r[1]), "=r"(r[2]), "=r"(r[3]) : "r"(addr));
}
__device__ __forceinline__ void lds128(uint32_t* r, uint32_t addr) {
    asm volatile("ld.shared.v4.b32 {%0,%1,%2,%3}, [%4];"
                 : "=r"(r[0]), "=r"(r[1]), "=r"(r[2]), "=r"(r[3]) : "r"(addr));
}
__device__ __forceinline__ void cp16(uint32_t dst, const void* src, int srcsize) {
    asm volatile("cp.async.cg.shared.global [%0], [%1], 16, %2;"
                 :: "r"(dst), "l"(src), "r"(srcsize));
}
__device__ __forceinline__ void cp_commit() {
    asm volatile("cp.async.commit_group;" ::: "memory");
}
__device__ __forceinline__ void cp_wait0() {
    asm volatile("cp.async.wait_group 0;" ::: "memory");
}
__device__ __forceinline__ void mma16816(float* d, const uint32_t* a, const uint32_t* b) {
    asm volatile("mma.sync.aligned.m16n8k16.row.col.f32.f16.f16.f32 "
                 "{%0,%1,%2,%3}, {%4,%5,%6,%7}, {%8,%9}, {%0,%1,%2,%3};"
                 : "+f"(d[0]), "+f"(d[1]), "+f"(d[2]), "+f"(d[3])
                 : "r"(a[0]), "r"(a[1]), "r"(a[2]), "r"(a[3]),
                   "r"(b[0]), "r"(b[1]));
}
__device__ __forceinline__ float gelu_f(float h) {
    return 0.5f * h * (1.0f + erff(h * 0.70710678118654752f));
}

// smem geometry (bytes)
#define A_STRIDE 80                         // 32 f16 (64B) + 16B pad: conflict-free ldsm
#define A_BUF    (128 * A_STRIDE)           // 10240
#define BP_BUF   8192                       // permuted B (fp16): 2048 words
#define SMEM_TOT (2 * A_BUF + 2 * BP_BUF)   // 36864

// ---------------- 0) pre-round x to fp16 -------------------------------------
__global__ void cvt_x_kernel(const float* __restrict__ x) {
    int idx = blockIdx.x * blockDim.x + threadIdx.x;
    if (idx >= T_TOK * DM / 4) return;
    float4 v = *(const float4*)(x + (size_t)idx * 4);
    uint2 w;
    w.x = pack_h2(v.x, v.y);
    w.y = pack_h2(v.z, v.w);
    *(uint2*)(g_xh + (size_t)idx * 4) = w;
}

// ---------------- 1) routing -------------------------------------------------
__global__ void route_kernel(const float* __restrict__ x,
                             const float* __restrict__ Wh) {
    int gw   = (blockIdx.x * blockDim.x + threadIdx.x) >> 5;
    int lane = threadIdx.x & 31;
    if (gw >= T_TOK) return;
    const float* xr = x + (size_t)gw * DM;
    float d0 = 0.f, d1 = 0.f;
    #pragma unroll
    for (int j = lane; j < DM; j += 32) {
        float v = xr[j];
        d0 = fmaf(v, Wh[j],      d0);
        d1 = fmaf(v, Wh[DM + j], d1);
    }
    #pragma unroll
    for (int o = 16; o > 0; o >>= 1) {
        d0 += __shfl_down_sync(0xffffffffu, d0, o);
        d1 += __shfl_down_sync(0xffffffffu, d1, o);
    }
    if (lane == 0) {
        g_flat_e[2 * gw]     = ((int)floorf(d0 * 8.0f)) & 63;
        g_flat_e[2 * gw + 1] = ((int)floorf(d1 * 8.0f)) & 63;
    }
}

// ---------------- 2) order-preserving rank -----------------------------------
__global__ void rank_kernel() {
    __shared__ int counts[NE];
    __shared__ int whist[32][NE];
    __shared__ int wpref[32][NE];
    __shared__ int ttot[NE];
    int tid  = threadIdx.x;
    int w    = tid >> 5;
    int lane = tid & 31;
    unsigned lmask = (1u << lane) - 1u;

    if (tid < NE) counts[tid] = 0;
    for (int j = tid; j < NE * CAPP; j += 1024) g_slot_tok[j] = -1;
    __syncthreads();

    for (int tile = 0; tile < (T_TOK * 2) / 1024; tile++) {
        for (int j = tid; j < 32 * NE; j += 1024) (&whist[0][0])[j] = 0;
        __syncthreads();

        int i = tile * 1024 + tid;
        int e = g_flat_e[i];
        unsigned m  = __match_any_sync(0xffffffffu, e);
        int prior   = __popc(m & lmask);
        if ((m & lmask) == 0) whist[w][e] = __popc(m);
        __syncthreads();

        if (tid < NE) {
            int s = 0;
            #pragma unroll
            for (int ww = 0; ww < 32; ww++) { wpref[ww][tid] = s; s += whist[ww][tid]; }
            ttot[tid] = s;
        }
        __syncthreads();

        int pos = counts[e] + wpref[w][e] + prior;
        if (pos < CAP) {
            g_entry_slot[i]            = e * CAPP + pos;
            g_slot_tok[e * CAPP + pos] = i >> 1;
        } else {
            g_entry_slot[i] = -1;
        }
        __syncthreads();
        if (tid < NE) counts[tid] += ttot[tid];
        __syncthreads();
    }
    if (tid < NE) g_cnt[tid] = counts[tid];
}

// Permuted-B (fp16) addressing: group (s=kstep16, wn), row q*8+g, word w=nf*2+h,
//  f = q ^ (wn<<1) ^ (g>>2); word pos = ((v^f)<<2)+(w&3), v=w>>2. Word = f16x2
//  {lo=B[k],hi=B[k+1]}, k = s*16 + 2q + 8h.

// ---------------- 3) GEMM1: H = gelu(gather(x_h) @ W1 + b1)  (fp16 mma) ------
// CTA 128m x 128n, 8 warps 4m x 2n, warp 32x64; BK=32 (2 ksteps of 16)
__global__ __launch_bounds__(256, 2) void xw1_kernel(
        const float* __restrict__ W1, const float* __restrict__ b1) {
    extern __shared__ char smem[];
    uint32_t sb = smem_u32(smem);
    int tid = threadIdx.x, lane = tid & 31, wid = tid >> 5;
    int wm = wid & 3, wn = wid >> 2;
    int g = lane >> 2, q = lane & 3;
    int n0 = blockIdx.x * 128, mt = blockIdx.y, e = blockIdx.z;

    if (mt * 128 >= g_cnt[e]) return;

    const float* Wb = W1 + (size_t)e * DM * DFF;

    int myrow = tid >> 1;
    int tok = g_slot_tok[e * CAPP + mt * 128 + myrow];

    float acc[2][8][4];
    #pragma unroll
    for (int mf = 0; mf < 2; mf++)
        #pragma unroll
        for (int nf = 0; nf < 8; nf++)
            #pragma unroll
            for (int j = 0; j < 4; j++) acc[mf][nf][j] = 0.f;

    float4 regB[4];

    // B writer: wid -> (h = wid>>2, qw = wid&3); item j = kstep s
    int hw = wid >> 2, qw = wid & 3;
    uint32_t boff[4];
    #pragma unroll
    for (int j = 0; j < 4; j++) {
        int n = lane * 4 + j;
        int wnn = n >> 6, nf = (n >> 3) & 7, gg = n & 7;
        int w = nf * 2 + hw, vv = w >> 2;
        int ff = qw ^ (wnn << 1) ^ (gg >> 2);
        boff[j] = (uint32_t)(((wnn * 32 + qw * 8 + gg) * 16 + ((vv ^ ff) << 2) + (w & 3)) * 4);
    }

    auto cpA = [&](int c) {
        int st = c & 1, k0 = c * 32;
        uint32_t dstb = sb + st * A_BUF + (uint32_t)myrow * A_STRIDE + (tid & 1) * 32;
        const __half* src = g_xh + (size_t)(tok >= 0 ? tok : 0) * DM + k0 + (tid & 1) * 16;
        cp16(dstb,      src,     tok >= 0 ? 16 : 0);
        cp16(dstb + 16, src + 8, tok >= 0 ? 16 : 0);
    };
    auto ldgB = [&](int k0) {
        #pragma unroll
        for (int j = 0; j < 2; j++) {
            int kk = k0 + j * 16 + 2 * wid;
            regB[j * 2]     = *(const float4*)(Wb + (size_t)kk * DFF + n0 + lane * 4);
            regB[j * 2 + 1] = *(const float4*)(Wb + (size_t)(kk + 1) * DFF + n0 + lane * 4);
        }
    };
    auto stsB = [&](int st) {
        char* Bb = smem + 2 * A_BUF + st * BP_BUF;
        #pragma unroll
        for (int j = 0; j < 2; j++) {
            char* base = Bb + j * 4096;
            const float* lo = (const float*)&regB[j * 2];
            const float* hi = (const float*)&regB[j * 2 + 1];
            #pragma unroll
            for (int jj = 0; jj < 4; jj++)
                *(uint32_t*)(base + boff[jj]) = pack_h2(lo[jj], hi[jj]);
        }
    };
    uint32_t a_off = (uint32_t)((wm * 32 + (lane & 15)) * A_STRIDE + (lane >> 4) * 16);
    int fr = q ^ (wn << 1) ^ (g >> 2);
    uint32_t bthr = (uint32_t)((wn * 32 + q * 8 + g) * 64);
    auto compute = [&](int st) {
        uint32_t Abase = sb + st * A_BUF;
        uint32_t Bst   = sb + 2 * A_BUF + st * BP_BUF + bthr;
        #pragma unroll
        for (int s = 0; s < 2; s++) {
            uint32_t af[2][4];
            ldsm4(af[0], Abase + a_off + s * 32);
            ldsm4(af[1], Abase + a_off + 16 * A_STRIDE + s * 32);
            uint32_t bw[16];
            uint32_t base = Bst + s * 4096;
            #pragma unroll
            for (int v = 0; v < 4; v++)
                lds128(&bw[v * 4], base + (uint32_t)(((v ^ fr) & 3) << 4));
            #pragma unroll
            for (int nf = 0; nf < 8; nf++) {
                mma16816(acc[0][nf], af[0], &bw[nf * 2]);
                mma16816(acc[1][nf], af[1], &bw[nf * 2]);
            }
        }
    };

    ldgB(0); cpA(0); cp_commit(); stsB(0); cp_wait0(); __syncthreads();
    #pragma unroll 1
    for (int c = 0; c < 16; c++) {
        if (c + 1 < 16) { ldgB((c + 1) * 32); cpA(c + 1); cp_commit(); }
        compute(c & 1);
        if (c + 1 < 16) { stsB((c + 1) & 1); cp_wait0(); __syncthreads(); }
    }

    const float* b1e = b1 + (size_t)e * DFF + n0;
    #pragma unroll
    for (int nf = 0; nf < 8; nf++) {
        int col = wn * 64 + nf * 8 + 2 * q;
        float2 bb = *(const float2*)(b1e + col);
        #pragma unroll
        for (int mf = 0; mf < 2; mf++) {
            int r0 = mt * 128 + wm * 32 + mf * 16 + g;
            __half* p0 = g_Hh + ((size_t)e * CAPP + r0) * DFF + n0 + col;
            *(uint32_t*)p0 = pack_h2(gelu_f(acc[mf][nf][0] + bb.x),
                                     gelu_f(acc[mf][nf][1] + bb.y));
            *(uint32_t*)(p0 + (size_t)8 * DFF) = pack_h2(gelu_f(acc[mf][nf][2] + bb.x),
                                                         gelu_f(acc[mf][nf][3] + bb.y));
        }
    }
}

// ---------------- 4) GEMM2: Y = H @ W2 + b2  (fp16 mma) ----------------------
__global__ __launch_bounds__(256, 2) void hw2_kernel(
        const float* __restrict__ W2, const float* __restrict__ b2) {
    extern __shared__ char smem[];
    uint32_t sb = smem_u32(smem);
    int tid = threadIdx.x, lane = tid & 31, wid = tid >> 5;
    int wm = wid & 3, wn = wid >> 2;
    int g = lane >> 2, q = lane & 3;
    int n0 = blockIdx.x * 128, mt = blockIdx.y, e = blockIdx.z;

    if (mt * 128 >= g_cnt[e]) return;

    const __half* Ab0 = g_Hh + ((size_t)e * CAPP + mt * 128) * DFF;
    const float*  Wb  = W2 + (size_t)e * DFF * DM;

    int myrow = tid >> 1;

    float acc[2][8][4];
    #pragma unroll
    for (int mf = 0; mf < 2; mf++)
        #pragma unroll
        for (int nf = 0; nf < 8; nf++)
            #pragma unroll
            for (int j = 0; j < 4; j++) acc[mf][nf][j] = 0.f;

    float4 regB[4];

    int hw = wid >> 2, qw = wid & 3;
    uint32_t boff[4];
    #pragma unroll
    for (int j = 0; j < 4; j++) {
        int n = lane * 4 + j;
        int wnn = n >> 6, nf = (n >> 3) & 7, gg = n & 7;
        int w = nf * 2 + hw, vv = w >> 2;
        int ff = qw ^ (wnn << 1) ^ (gg >> 2);
        boff[j] = (uint32_t)(((wnn * 32 + qw * 8 + gg) * 16 + ((vv ^ ff) << 2) + (w & 3)) * 4);
    }

    auto cpA = [&](int c) {
        int st = c & 1, k0 = c * 32;
        uint32_t dstb = sb + st * A_BUF + (uint32_t)myrow * A_STRIDE + (tid & 1) * 32;
        const __half* src = Ab0 + (size_t)myrow * DFF + k0 + (tid & 1) * 16;
        cp16(dstb,      src,     16);
        cp16(dstb + 16, src + 8, 16);
    };
    auto ldgB = [&](int k0) {
        #pragma unroll
        for (int j = 0; j < 2; j++) {
            int kk = k0 + j * 16 + 2 * wid;
            regB[j * 2]     = *(const float4*)(Wb + (size_t)kk * DM + n0 + lane * 4);
            regB[j * 2 + 1] = *(const float4*)(Wb + (size_t)(kk + 1) * DM + n0 + lane * 4);
        }
    };
    auto stsB = [&](int st) {
        char* Bb = smem + 2 * A_BUF + st * BP_BUF;
        #pragma unroll
        for (int j = 0; j < 2; j++) {
            char* base = Bb + j * 4096;
            const float* lo = (const float*)&regB[j * 2];
            const float* hi = (const float*)&regB[j * 2 + 1];
            #pragma unroll
            for (int jj = 0; jj < 4; jj++)
                *(uint32_t*)(base + boff[jj]) = pack_h2(lo[jj], hi[jj]);
        }
    };
    uint32_t a_off = (uint32_t)((wm * 32 + (lane & 15)) * A_STRIDE + (lane >> 4) * 16);
    int fr = q ^ (wn << 1) ^ (g >> 2);
    uint32_t bthr = (uint32_t)((wn * 32 + q * 8 + g) * 64);
    auto compute = [&](int st) {
        uint32_t Abase = sb + st * A_BUF;
        uint32_t Bst   = sb + 2 * A_BUF + st * BP_BUF + bthr;
        #pragma unroll
        for (int s = 0; s < 2; s++) {
            uint32_t af[2][4];
            ldsm4(af[0], Abase + a_off + s * 32);
            ldsm4(af[1], Abase + a_off + 16 * A_STRIDE + s * 32);
            uint32_t bw[16];
            uint32_t base = Bst + s * 4096;
            #pragma unroll
            for (int v = 0; v < 4; v++)
                lds128(&bw[v * 4], base + (uint32_t)(((v ^ fr) & 3) << 4));
            #pragma unroll
            for (int nf = 0; nf < 8; nf++) {
                mma16816(acc[0][nf], af[0], &bw[nf * 2]);
                mma16816(acc[1][nf], af[1], &bw[nf * 2]);
            }
        }
    };

    ldgB(0); cpA(0); cp_commit(); stsB(0); cp_wait0(); __syncthreads();
    #pragma unroll 1
    for (int c = 0; c < 64; c++) {
        if (c + 1 < 64) { ldgB((c + 1) * 32); cpA(c + 1); cp_commit(); }
        compute(c & 1);
        if (c + 1 < 64) { stsB((c + 1) & 1); cp_wait0(); __syncthreads(); }
    }

    const float* b2e = b2 + (size_t)e * DM + n0;
    #pragma unroll
    for (int nf = 0; nf < 8; nf++) {
        int col = wn * 64 + nf * 8 + 2 * q;
        float2 bb = *(const float2*)(b2e + col);
        #pragma unroll
        for (int mf = 0; mf < 2; mf++) {
            int r0 = mt * 128 + wm * 32 + mf * 16 + g;
            float* p0 = g_Y + ((size_t)e * CAPP + r0) * DM + n0 + col;
            float2 o0 = make_float2(acc[mf][nf][0] + bb.x, acc[mf][nf][1] + bb.y);
            *(float2*)p0 = o0;
            float2 o1 = make_float2(acc[mf][nf][2] + bb.x, acc[mf][nf][3] + bb.y);
            *(float2*)(p0 + 8 * DM) = o1;
        }
    }
}

// ---------------- 5) output gather + mean ------------------------------------
__global__ void out_kernel(float* __restrict__ out) {
    int idx = blockIdx.x * blockDim.x + threadIdx.x;
    if (idx >= T_TOK * DM / 4) return;
    int t  = idx / (DM / 4);
    int d4 = (idx % (DM / 4)) * 4;
    int s0 = g_entry_slot[2 * t];
    int s1 = g_entry_slot[2 * t + 1];
    float4 r = make_float4(0.f, 0.f, 0.f, 0.f);
    if (s0 >= 0) {
        float4 v = *(const float4*)(g_Y + (size_t)s0 * DM + d4);
        r.x += v.x; r.y += v.y; r.z += v.z; r.w += v.w;
    }
    if (s1 >= 0) {
        float4 v = *(const float4*)(g_Y + (size_t)s1 * DM + d4);
        r.x += v.x; r.y += v.y; r.z += v.z; r.w += v.w;
    }
    r.x *= 0.5f; r.y *= 0.5f; r.z *= 0.5f; r.w *= 0.5f;
    *(float4*)(out + (size_t)idx * 4) = r;
}

// ---------------- launch -----------------------------------------------------
extern "C" void kernel_launch(void* const* d_in, const int* in_sizes, int n_in,
                              void* d_out, int out_size) {
    const float* x   = (const float*)d_in[0];
    const float* Wh  = (const float*)d_in[1];
    const float* W1  = (const float*)d_in[2];
    const float* b1  = (const float*)d_in[3];
    const float* W2  = (const float*)d_in[4];
    const float* b2  = (const float*)d_in[5];
    float* out = (float*)d_out;

    route_kernel<<<T_TOK / 8, 256>>>(x, Wh);
    cvt_x_kernel<<<(T_TOK * DM / 4 + 255) / 256, 256>>>(x);
    rank_kernel<<<1, 1024>>>();
    xw1_kernel<<<dim3(DFF / 128, CAPP / 128, NE), 256, SMEM_TOT>>>(W1, b1);
    hw2_kernel<<<dim3(DM / 128, CAPP / 128, NE), 256, SMEM_TOT>>>(W2, b2);
    out_kernel<<<(T_TOK * DM / 4 + 255) / 256, 256>>>(out);
}